// round 11
// baseline (speedup 1.0000x reference)
#include <cuda_runtime.h>
#include <cstdint>

#define NN 50000
#define NG 64
#define MAXE 800000
#define MAXE2 (MAXE + NN)
#define MAXH 512
#define BN_EPS 1e-5f
#define SCAN_B 1024
#define NSTR 250

// ================= scratch (device globals) ===================================
__device__ __align__(16) float g_h[(size_t)NN * MAXH];     // GEMM "message" output
__device__ __align__(16) float g_agg[(size_t)NN * MAXH];   // conv out (ping)
__device__ __align__(16) float g_act[(size_t)NN * MAXH];   // conv out (pong) / pre-agg x
__device__ float g_dinv[NN];
__device__ int   g_cnt[NN];
__device__ int   g_cursor[NN];
__device__ int   g_off[NN + 1];
__device__ int   g_bsum[64];
__device__ int   g_csrc[MAXE2];
__device__ float g_cw[MAXE2];
__device__ float g_psum[NSTR * MAXH];
__device__ float g_psqs[NSTR * MAXH];
__device__ __align__(16) float g_mean[MAXH];
__device__ __align__(16) float g_scale[MAXH];
__device__ int   g_gstart[NG + 1];

// ================= CSR build ===================================================
__global__ void k_zeroi(int* p, int n) {
    int i = blockIdx.x * blockDim.x + threadIdx.x;
    if (i < n) p[i] = 0;
}
__global__ void k_count(const int* __restrict__ col, int* cnt, int E) {
    int i = blockIdx.x * blockDim.x + threadIdx.x;
    if (i < E) atomicAdd(&cnt[col[i]], 1);
}
// scan over (cnt[i] + 1): each node gets one extra slot for its self-edge
__global__ void k_scan1(const int* __restrict__ cnt, int* off, int* bsum, int n) {
    __shared__ int sh[SCAN_B];
    int i = blockIdx.x * SCAN_B + threadIdx.x;
    sh[threadIdx.x] = (i < n) ? (cnt[i] + 1) : 0;
    __syncthreads();
#pragma unroll
    for (int d = 1; d < SCAN_B; d <<= 1) {
        int t = (threadIdx.x >= d) ? sh[threadIdx.x - d] : 0;
        __syncthreads();
        sh[threadIdx.x] += t;
        __syncthreads();
    }
    if (i < n) off[i + 1] = sh[threadIdx.x];
    if (threadIdx.x == SCAN_B - 1) bsum[blockIdx.x] = sh[SCAN_B - 1];
}
__global__ void k_scan2(int* bsum, int nb, int* off) {
    if (threadIdx.x == 0) {
        off[0] = 0;
        int s = 0;
        for (int b = 0; b < nb; b++) { s += bsum[b]; bsum[b] = s; }
    }
}
__global__ void k_scan3(int* off, const int* __restrict__ bsum, int n) {
    int b = blockIdx.x + 1;
    int i = b * SCAN_B + threadIdx.x;
    if (i < n) off[i + 1] += bsum[b - 1];
}
__global__ void k_dinv2(const int* __restrict__ cnt, float* dinv, int n) {
    int i = blockIdx.x * blockDim.x + threadIdx.x;
    if (i < n) dinv[i] = rsqrtf((float)(cnt[i] + 1));
}
// self-edge at slot off[n]; cursor starts at 1
__global__ void k_selfplace(const int* __restrict__ off, const float* __restrict__ dinv,
                            int* cursor, int* csrc, float* cw, int n) {
    int i = blockIdx.x * blockDim.x + threadIdx.x;
    if (i >= n) return;
    int p = off[i];
    csrc[p] = i;
    float d = dinv[i];
    cw[p] = d * d;
    cursor[i] = 1;
}
__global__ void k_place(const int* __restrict__ row, const int* __restrict__ col,
                        const float* __restrict__ dinv, const int* __restrict__ off,
                        int* cursor, int* csrc, float* cw, int E) {
    int e = blockIdx.x * blockDim.x + threadIdx.x;
    if (e >= E) return;
    int d = col[e], r = row[e];
    int pos = off[d] + atomicAdd(&cursor[d], 1);
    csrc[pos] = r;
    cw[pos] = dinv[r] * dinv[d];
}

// ================= SIMT GEMM (TBK=32, double-buffered, BN-in-A-load, FFMA2) ====
// OUT = act(A)[M,K] @ B[K,N] (+ bias if ADDB); act = BN+ReLU when BN.
#define TBM 128
#define TBN 128
#define TBK 32
#define ASTR 132
#define AS_SZ (2 * TBK * ASTR)          // floats
#define BS_SZ (2 * TBK * TBN)
#define SMEM_GEMM ((AS_SZ + BS_SZ) * 4) // 66560 B

template <bool BN, bool ADDB>
__global__ __launch_bounds__(256, 2)
void k_gemm_fused(const float* __restrict__ A, const float* __restrict__ B,
                  float* __restrict__ OUT, const float* __restrict__ bias,
                  const float* __restrict__ meanK, const float* __restrict__ scaleK,
                  const float* __restrict__ beK,
                  int M, int K, int N) {
    extern __shared__ float smf[];
    float* As = smf;                     // [2][TBK][ASTR]
    float* Bs = smf + AS_SZ;             // [2][TBK][TBN]

    const int tid = threadIdx.x;
    const int rowBase = blockIdx.y * TBM;
    const int colBase = blockIdx.x * TBN;

    // A loader: fixed cols ac..ac+3, rows ar + 32s (s=0..3)
    const int ar = tid >> 3;             // 0..31
    const int ac = (tid & 7) << 2;       // 0..28
    // B loader: fixed cols bc..bc+3, rows br + 8s (s=0..3)
    const int br = tid >> 5;             // 0..7
    const int bc = (tid & 31) << 2;
    const int tx = tid & 15;
    const int ty = tid >> 4;

    unsigned long long acc2[8][4];
#pragma unroll
    for (int i = 0; i < 8; i++)
#pragma unroll
        for (int j = 0; j < 4; j++) acc2[i][j] = 0ULL;

    const int nk = K / TBK;

    // ---- load chunk 0 ----
    {
        float4 mn, sc, be;
        if (BN) {
            mn = *(const float4*)&meanK[ac];
            sc = *(const float4*)&scaleK[ac];
            be = *(const float4*)&beK[ac];
        }
#pragma unroll
        for (int s = 0; s < 4; s++) {
            int kk = ar;                 // k index within chunk? no: rows are k? A tile is [row m][col k]
            (void)kk;
            int r = (tid >> 3) + 0;      // placeholder (rewritten below)
            (void)r;
            break;
        }
        // A tile: 128 rows (m) x 32 cols (k). Thread covers col ac..ac+3, rows ar+32s.
#pragma unroll
        for (int s = 0; s < 4; s++) {
            int m = ar + s * 32;
            int gr = rowBase + m;
            float4 v = make_float4(0.f, 0.f, 0.f, 0.f);
            if (gr < M) {
                v = *(const float4*)&A[(size_t)gr * K + ac];
                if (BN) {
                    v.x = fmaxf((v.x - mn.x) * sc.x + be.x, 0.f);
                    v.y = fmaxf((v.y - mn.y) * sc.y + be.y, 0.f);
                    v.z = fmaxf((v.z - mn.z) * sc.z + be.z, 0.f);
                    v.w = fmaxf((v.w - mn.w) * sc.w + be.w, 0.f);
                }
            }
            As[(ac + 0) * ASTR + m] = v.x;
            As[(ac + 1) * ASTR + m] = v.y;
            As[(ac + 2) * ASTR + m] = v.z;
            As[(ac + 3) * ASTR + m] = v.w;
        }
#pragma unroll
        for (int s = 0; s < 4; s++) {
            int k = br + s * 8;
            *(float4*)&Bs[k * TBN + bc] = *(const float4*)&B[(size_t)k * N + colBase + bc];
        }
    }
    __syncthreads();

    for (int kt = 0; kt < nk; kt++) {
        int buf = kt & 1;
        if (kt + 1 < nk) {
            int k0 = (kt + 1) * TBK;
            int dstA = (buf ^ 1) * TBK * ASTR;
            int dstB = (buf ^ 1) * TBK * TBN;
            float4 mn, sc, be;
            if (BN) {
                mn = *(const float4*)&meanK[k0 + ac];
                sc = *(const float4*)&scaleK[k0 + ac];
                be = *(const float4*)&beK[k0 + ac];
            }
#pragma unroll
            for (int s = 0; s < 4; s++) {
                int m = ar + s * 32;
                int gr = rowBase + m;
                float4 v = make_float4(0.f, 0.f, 0.f, 0.f);
                if (gr < M) {
                    v = *(const float4*)&A[(size_t)gr * K + k0 + ac];
                    if (BN) {
                        v.x = fmaxf((v.x - mn.x) * sc.x + be.x, 0.f);
                        v.y = fmaxf((v.y - mn.y) * sc.y + be.y, 0.f);
                        v.z = fmaxf((v.z - mn.z) * sc.z + be.z, 0.f);
                        v.w = fmaxf((v.w - mn.w) * sc.w + be.w, 0.f);
                    }
                }
                As[dstA + (ac + 0) * ASTR + m] = v.x;
                As[dstA + (ac + 1) * ASTR + m] = v.y;
                As[dstA + (ac + 2) * ASTR + m] = v.z;
                As[dstA + (ac + 3) * ASTR + m] = v.w;
            }
#pragma unroll
            for (int s = 0; s < 4; s++) {
                int k = br + s * 8;
                *(float4*)&Bs[dstB + k * TBN + bc] =
                    *(const float4*)&B[(size_t)(k0 + k) * N + colBase + bc];
            }
        }

        const float* Ab = As + buf * TBK * ASTR;
        const float* Bb = Bs + buf * TBK * TBN;
#pragma unroll
        for (int k = 0; k < TBK; k++) {
            float a[8], b[8];
            *(float4*)&a[0] = *(const float4*)&Ab[k * ASTR + ty * 4];
            *(float4*)&a[4] = *(const float4*)&Ab[k * ASTR + ty * 4 + 64];
            *(float4*)&b[0] = *(const float4*)&Bb[k * TBN + tx * 4];
            *(float4*)&b[4] = *(const float4*)&Bb[k * TBN + tx * 4 + 64];
            unsigned long long bp[4];
#pragma unroll
            for (int j = 0; j < 4; j++)
                asm("mov.b64 %0, {%1, %2};"
                    : "=l"(bp[j]) : "f"(b[j * 2]), "f"(b[j * 2 + 1]));
#pragma unroll
            for (int i = 0; i < 8; i++) {
                unsigned long long ap;
                asm("mov.b64 %0, {%1, %1};" : "=l"(ap) : "f"(a[i]));
#pragma unroll
                for (int j = 0; j < 4; j++)
                    asm("fma.rn.f32x2 %0, %1, %2, %0;"
                        : "+l"(acc2[i][j]) : "l"(ap), "l"(bp[j]));
            }
        }
        __syncthreads();
    }

    float blo[8] = {0, 0, 0, 0, 0, 0, 0, 0};
    if (ADDB) {
        float4 bl0 = *(const float4*)&bias[colBase + tx * 4];
        float4 bl1 = *(const float4*)&bias[colBase + tx * 4 + 64];
        blo[0] = bl0.x; blo[1] = bl0.y; blo[2] = bl0.z; blo[3] = bl0.w;
        blo[4] = bl1.x; blo[5] = bl1.y; blo[6] = bl1.z; blo[7] = bl1.w;
    }

#pragma unroll
    for (int i = 0; i < 8; i++) {
        int r = (i < 4) ? (ty * 4 + i) : (ty * 4 + 64 + i - 4);
        int gr = rowBase + r;
        if (gr >= M) continue;
        size_t base = (size_t)gr * N;
#pragma unroll
        for (int jj = 0; jj < 2; jj++) {
            int c = colBase + tx * 4 + jj * 64;
            float c0, c1, c2, c3;
            asm("mov.b64 {%0, %1}, %2;" : "=f"(c0), "=f"(c1) : "l"(acc2[i][jj * 2 + 0]));
            asm("mov.b64 {%0, %1}, %2;" : "=f"(c2), "=f"(c3) : "l"(acc2[i][jj * 2 + 1]));
            float4 hv;
            if (ADDB)
                hv = make_float4(c0 + blo[jj * 4 + 0], c1 + blo[jj * 4 + 1],
                                 c2 + blo[jj * 4 + 2], c3 + blo[jj * 4 + 3]);
            else
                hv = make_float4(c0, c1, c2, c3);
            *(float4*)&OUT[base + c] = hv;
        }
    }
}

// ================= CSR gather (self-edges included; bias as init) ===============
template <bool BIAS>
__global__ void k_gather(const float* __restrict__ src, const int* __restrict__ csrc,
                         const float* __restrict__ cw, const int* __restrict__ off,
                         const float* __restrict__ bias, float* __restrict__ outp,
                         int H, int tpnshift) {
    int tpn = 1 << tpnshift;
    int local = threadIdx.x >> tpnshift;
    int node = blockIdx.x * (blockDim.x >> tpnshift) + local;
    if (node >= NN) return;
    int c = (threadIdx.x & (tpn - 1)) << 2;
    int s = __ldg(&off[node]);
    int e = __ldg(&off[node + 1]);
    float ax = 0.f, ay = 0.f, az = 0.f, aw = 0.f;
    if (BIAS) {
        float4 b = __ldg((const float4*)(bias + c));
        ax = b.x; ay = b.y; az = b.z; aw = b.w;
    }
    for (int i = s; i < e; i++) {
        int sn = __ldg(&csrc[i]);
        float w = __ldg(&cw[i]);
        float4 v = __ldg((const float4*)(src + (size_t)sn * H + c));
        ax += v.x * w; ay += v.y * w; az += v.z * w; aw += v.w * w;
    }
    *(float4*)&outp[(size_t)node * H + c] = make_float4(ax, ay, az, aw);
}

// ================= BN stats: stripe partials (fp32) + fp64 combine ==============
__global__ void k_stats_part(const float* __restrict__ x, int H,
                             float* __restrict__ psum, float* __restrict__ psqs) {
    int c = blockIdx.x * blockDim.x + threadIdx.x;
    int st = blockIdx.y;
    if (c >= H) return;
    float s = 0.f, q = 0.f;
    for (int r = st; r < NN; r += NSTR) {
        float v = x[(size_t)r * H + c];
        s += v;
        q += v * v;
    }
    psum[st * H + c] = s;
    psqs[st * H + c] = q;
}
__global__ void k_bnparam(const float* __restrict__ psum, const float* __restrict__ psqs,
                          const float* __restrict__ g, float* __restrict__ mean,
                          float* __restrict__ scale, int H) {
    int c = blockIdx.x * blockDim.x + threadIdx.x;
    if (c >= H) return;
    double s = 0.0, q = 0.0;
    for (int st = 0; st < NSTR; st++) {
        s += (double)psum[st * H + c];
        q += (double)psqs[st * H + c];
    }
    const double invN = 1.0 / (double)NN;
    double m = s * invN;
    double var = q * invN - m * m;
    mean[c] = (float)m;
    scale[c] = g[c] * (float)rsqrt(var + (double)BN_EPS);
}

// ================= graph boundaries + pool head =================================
__global__ void k_bounds(const int* __restrict__ batch, int* gstart, int n) {
    int i = blockIdx.x * blockDim.x + threadIdx.x;
    if (i >= n) return;
    int bi = batch[i];
    int bp = (i == 0) ? -1 : batch[i - 1];
    for (int g = bp + 1; g <= bi; g++) gstart[g] = i;
    if (i == n - 1)
        for (int g = bi + 1; g <= NG; g++) gstart[g] = n;
}
__global__ void k_pool_head(const float* __restrict__ agg, const int* __restrict__ gstart,
                            const float* __restrict__ mean, const float* __restrict__ scale,
                            const float* __restrict__ be, const float* __restrict__ Wo,
                            const float* __restrict__ bo, float* __restrict__ out) {
    __shared__ float pooled[128];
    int g = blockIdx.x;
    int c = threadIdx.x;
    int s = gstart[g], e = gstart[g + 1];
    float mn = mean[c], sc = scale[c], bb = be[c];
    float acc = 0.f;
    for (int n = s; n < e; n++)
        acc += fmaxf((agg[(size_t)n * 128 + c] - mn) * sc + bb, 0.f);
    float inv = 1.0f / (float)max(e - s, 1);
    pooled[c] = acc * inv;
    __syncthreads();
    if (c < 10) {
        float o = bo[c];
#pragma unroll 8
        for (int k = 0; k < 128; k++)
            o += pooled[k] * Wo[k * 10 + c];
        out[g * 10 + c] = o;
    }
}

// ================= host orchestration ===========================================
static inline int ilog2(int v) { int s = 0; while ((1 << s) < v) s++; return s; }

extern "C" void kernel_launch(void* const* d_in, const int* in_sizes, int n_in,
                              void* d_out, int out_size) {
    const float* x     = (const float*)d_in[0];
    const int*   ei    = (const int*)d_in[1];
    const int*   batch = (const int*)d_in[2];
    const float* W1 = (const float*)d_in[3];  const float* b1 = (const float*)d_in[4];
    const float* g1 = (const float*)d_in[5];  const float* be1 = (const float*)d_in[6];
    const float* W2 = (const float*)d_in[7];  const float* b2 = (const float*)d_in[8];
    const float* g2 = (const float*)d_in[9];  const float* be2 = (const float*)d_in[10];
    const float* W3 = (const float*)d_in[11]; const float* b3 = (const float*)d_in[12];
    const float* g3 = (const float*)d_in[13]; const float* be3 = (const float*)d_in[14];
    const float* Wo = (const float*)d_in[15]; const float* bo = (const float*)d_in[16];
    float* out = (float*)d_out;

    int E = in_sizes[1] / 2;
    const int* row = ei;
    const int* col = ei + E;

    float *h, *agg, *act, *dinv, *mean, *scale, *cw, *psum, *psqs;
    int *cnt, *cursor, *off, *bsum, *csrc, *gstart;
    cudaGetSymbolAddress((void**)&h, g_h);
    cudaGetSymbolAddress((void**)&agg, g_agg);
    cudaGetSymbolAddress((void**)&act, g_act);
    cudaGetSymbolAddress((void**)&dinv, g_dinv);
    cudaGetSymbolAddress((void**)&mean, g_mean);
    cudaGetSymbolAddress((void**)&scale, g_scale);
    cudaGetSymbolAddress((void**)&cw, g_cw);
    cudaGetSymbolAddress((void**)&psum, g_psum);
    cudaGetSymbolAddress((void**)&psqs, g_psqs);
    cudaGetSymbolAddress((void**)&cnt, g_cnt);
    cudaGetSymbolAddress((void**)&cursor, g_cursor);
    cudaGetSymbolAddress((void**)&off, g_off);
    cudaGetSymbolAddress((void**)&bsum, g_bsum);
    cudaGetSymbolAddress((void**)&csrc, g_csrc);
    cudaGetSymbolAddress((void**)&gstart, g_gstart);

    cudaFuncSetAttribute(k_gemm_fused<false, true>,
                         cudaFuncAttributeMaxDynamicSharedMemorySize, SMEM_GEMM);
    cudaFuncSetAttribute(k_gemm_fused<true, false>,
                         cudaFuncAttributeMaxDynamicSharedMemorySize, SMEM_GEMM);

    // ---- CSR build + dinv (self-edges included) ----
    int nb = (NN + SCAN_B - 1) / SCAN_B;
    k_zeroi<<<(NN + 255) / 256, 256>>>(cnt, NN);                         // 1
    k_count<<<(E + 255) / 256, 256>>>(col, cnt, E);                      // 2
    k_scan1<<<nb, SCAN_B>>>(cnt, off, bsum, NN);                         // 3
    // 4: tiny GEMM clone at the ncu-profiled launch slot (negligible time,
    //    gives us SASS/pipe profile of the real GEMM next round)
    {
        dim3 grid(2, 8);
        k_gemm_fused<false, true><<<grid, 256, SMEM_GEMM>>>(
            agg, W2, h, b2, nullptr, nullptr, nullptr, 1024, 512, 256);
    }
    k_scan2<<<1, 32>>>(bsum, nb, off);                                   // 5
    if (nb > 1) k_scan3<<<nb - 1, SCAN_B>>>(off, bsum, NN);              // 6
    k_dinv2<<<(NN + 255) / 256, 256>>>(cnt, dinv, NN);                   // 7
    k_selfplace<<<(NN + 255) / 256, 256>>>(off, dinv, cursor, csrc, cw, NN); // 8
    k_place<<<(E + 255) / 256, 256>>>(row, col, dinv, off, cursor, csrc, cw, E); // 9
    k_bounds<<<(NN + 255) / 256, 256>>>(batch, gstart, NN);              // 10

    const int GY = (NN + TBM - 1) / TBM;

    // ---- layer 1: pre-aggregate x (width 128, self-edge in CSR), GEMM+bias ----
    k_gather<false><<<(NN + 3) / 4, 128>>>(x, csrc, cw, off, nullptr, act, 128,
                                           ilog2(128 / 4));
    {
        dim3 grid(512 / TBN, GY);
        k_gemm_fused<false, true><<<grid, 256, SMEM_GEMM>>>(
            act, W1, agg, b1, nullptr, nullptr, nullptr, NN, 128, 512);
    }
    {
        dim3 sgrid((512 + 127) / 128, NSTR);
        k_stats_part<<<sgrid, 128>>>(agg, 512, psum, psqs);
    }

    // ---- layer 2: BN fused in GEMM A-load; gather adds bias ----
    k_bnparam<<<(512 + 127) / 128, 128>>>(psum, psqs, g1, mean, scale, 512);
    {
        dim3 grid(256 / TBN, GY);
        k_gemm_fused<true, false><<<grid, 256, SMEM_GEMM>>>(
            agg, W2, h, nullptr, mean, scale, be1, NN, 512, 256);
    }
    k_gather<true><<<(NN + 1) / 2, 128>>>(h, csrc, cw, off, b2, act, 256,
                                          ilog2(256 / 4));
    {
        dim3 sgrid((256 + 127) / 128, NSTR);
        k_stats_part<<<sgrid, 128>>>(act, 256, psum, psqs);
    }

    // ---- layer 3 ----
    k_bnparam<<<(256 + 127) / 128, 128>>>(psum, psqs, g2, mean, scale, 256);
    {
        dim3 grid(128 / TBN, GY);
        k_gemm_fused<true, false><<<grid, 256, SMEM_GEMM>>>(
            act, W3, h, nullptr, mean, scale, be2, NN, 256, 128);
    }
    k_gather<true><<<(NN + 3) / 4, 128>>>(h, csrc, cw, off, b3, agg, 128,
                                          ilog2(128 / 4));
    {
        dim3 sgrid(1, NSTR);
        k_stats_part<<<sgrid, 128>>>(agg, 128, psum, psqs);
    }

    // ---- final BN + pool + head ----
    k_bnparam<<<1, 128>>>(psum, psqs, g3, mean, scale, 128);
    k_pool_head<<<NG, 128>>>(agg, gstart, mean, scale, be3, Wo, bo, out);
}

// round 12
// speedup vs baseline: 1.0656x; 1.0656x over previous
#include <cuda_runtime.h>
#include <cstdint>

#define NN 50000
#define NG 64
#define MAXE 800000
#define MAXE2 (MAXE + NN)
#define MAXH 512
#define BN_EPS 1e-5f
#define SCAN_B 1024
#define NSTR 250

// ================= scratch (device globals) ===================================
__device__ __align__(16) float g_h[(size_t)NN * MAXH];     // GEMM "message" output
__device__ __align__(16) float g_agg[(size_t)NN * MAXH];   // conv out (ping)
__device__ __align__(16) float g_act[(size_t)NN * MAXH];   // conv out (pong) / pre-agg x
__device__ float g_dinv[NN];
__device__ int   g_cnt[NN];
__device__ int   g_cursor[NN];
__device__ int   g_off[NN + 1];
__device__ int   g_bsum[64];
__device__ int   g_csrc[MAXE2];
__device__ float g_cw[MAXE2];
__device__ float g_psum[NSTR * MAXH];
__device__ float g_psqs[NSTR * MAXH];
__device__ __align__(16) float g_mean[MAXH];
__device__ __align__(16) float g_scale[MAXH];
__device__ int   g_gstart[NG + 1];

// ================= CSR build ===================================================
__global__ void k_zeroi(int* p, int n) {
    int i = blockIdx.x * blockDim.x + threadIdx.x;
    if (i < n) p[i] = 0;
}
__global__ void k_count(const int* __restrict__ col, int* cnt, int E) {
    int i = blockIdx.x * blockDim.x + threadIdx.x;
    if (i < E) atomicAdd(&cnt[col[i]], 1);
}
// scan over (cnt[i] + 1): each node gets one extra slot for its self-edge
__global__ void k_scan1(const int* __restrict__ cnt, int* off, int* bsum, int n) {
    __shared__ int sh[SCAN_B];
    int i = blockIdx.x * SCAN_B + threadIdx.x;
    sh[threadIdx.x] = (i < n) ? (cnt[i] + 1) : 0;
    __syncthreads();
#pragma unroll
    for (int d = 1; d < SCAN_B; d <<= 1) {
        int t = (threadIdx.x >= d) ? sh[threadIdx.x - d] : 0;
        __syncthreads();
        sh[threadIdx.x] += t;
        __syncthreads();
    }
    if (i < n) off[i + 1] = sh[threadIdx.x];
    if (threadIdx.x == SCAN_B - 1) bsum[blockIdx.x] = sh[SCAN_B - 1];
}
__global__ void k_scan2(int* bsum, int nb, int* off) {
    if (threadIdx.x == 0) {
        off[0] = 0;
        int s = 0;
        for (int b = 0; b < nb; b++) { s += bsum[b]; bsum[b] = s; }
    }
}
__global__ void k_scan3(int* off, const int* __restrict__ bsum, int n) {
    int b = blockIdx.x + 1;
    int i = b * SCAN_B + threadIdx.x;
    if (i < n) off[i + 1] += bsum[b - 1];
}
__global__ void k_dinv2(const int* __restrict__ cnt, float* dinv, int n) {
    int i = blockIdx.x * blockDim.x + threadIdx.x;
    if (i < n) dinv[i] = rsqrtf((float)(cnt[i] + 1));
}
// self-edge at slot off[n]; cursor starts at 1
__global__ void k_selfplace(const int* __restrict__ off, const float* __restrict__ dinv,
                            int* cursor, int* csrc, float* cw, int n) {
    int i = blockIdx.x * blockDim.x + threadIdx.x;
    if (i >= n) return;
    int p = off[i];
    csrc[p] = i;
    float d = dinv[i];
    cw[p] = d * d;
    cursor[i] = 1;
}
__global__ void k_place(const int* __restrict__ row, const int* __restrict__ col,
                        const float* __restrict__ dinv, const int* __restrict__ off,
                        int* cursor, int* csrc, float* cw, int E) {
    int e = blockIdx.x * blockDim.x + threadIdx.x;
    if (e >= E) return;
    int d = col[e], r = row[e];
    int pos = off[d] + atomicAdd(&cursor[d], 1);
    csrc[pos] = r;
    cw[pos] = dinv[r] * dinv[d];
}

// ================= SIMT GEMM (TBK=32, double-buffered, BN-in-A-load, FFMA2) ====
// OUT = act(A)[M,K] @ B[K,N] (+ bias if ADDB); act = BN+ReLU when BN.
#define TBM 128
#define TBN 128
#define TBK 32
#define ASTR 132
#define AS_SZ (2 * TBK * ASTR)          // floats
#define BS_SZ (2 * TBK * TBN)
#define SMEM_GEMM ((AS_SZ + BS_SZ) * 4) // 66560 B

template <bool BN, bool ADDB>
__global__ __launch_bounds__(256, 2)
void k_gemm_fused(const float* __restrict__ A, const float* __restrict__ B,
                  float* __restrict__ OUT, const float* __restrict__ bias,
                  const float* __restrict__ meanK, const float* __restrict__ scaleK,
                  const float* __restrict__ beK,
                  int M, int K, int N) {
    extern __shared__ float smf[];
    float* As = smf;                     // [2][TBK][ASTR]
    float* Bs = smf + AS_SZ;             // [2][TBK][TBN]

    const int tid = threadIdx.x;
    const int rowBase = blockIdx.y * TBM;
    const int colBase = blockIdx.x * TBN;

    const int ar = tid >> 3;             // 0..31
    const int ac = (tid & 7) << 2;       // 0..28
    const int br = tid >> 5;             // 0..7
    const int bc = (tid & 31) << 2;
    const int tx = tid & 15;
    const int ty = tid >> 4;

    unsigned long long acc2[8][4];
#pragma unroll
    for (int i = 0; i < 8; i++)
#pragma unroll
        for (int j = 0; j < 4; j++) acc2[i][j] = 0ULL;

    const int nk = K / TBK;

    // ---- load chunk 0 ----
    {
        float4 mn, sc, be;
        if (BN) {
            mn = *(const float4*)&meanK[ac];
            sc = *(const float4*)&scaleK[ac];
            be = *(const float4*)&beK[ac];
        }
#pragma unroll
        for (int s = 0; s < 4; s++) {
            int m = ar + s * 32;
            int gr = rowBase + m;
            float4 v = make_float4(0.f, 0.f, 0.f, 0.f);
            if (gr < M) {
                v = *(const float4*)&A[(size_t)gr * K + ac];
                if (BN) {
                    v.x = fmaxf((v.x - mn.x) * sc.x + be.x, 0.f);
                    v.y = fmaxf((v.y - mn.y) * sc.y + be.y, 0.f);
                    v.z = fmaxf((v.z - mn.z) * sc.z + be.z, 0.f);
                    v.w = fmaxf((v.w - mn.w) * sc.w + be.w, 0.f);
                }
            }
            As[(ac + 0) * ASTR + m] = v.x;
            As[(ac + 1) * ASTR + m] = v.y;
            As[(ac + 2) * ASTR + m] = v.z;
            As[(ac + 3) * ASTR + m] = v.w;
        }
#pragma unroll
        for (int s = 0; s < 4; s++) {
            int k = br + s * 8;
            *(float4*)&Bs[k * TBN + bc] = *(const float4*)&B[(size_t)k * N + colBase + bc];
        }
    }
    __syncthreads();

    for (int kt = 0; kt < nk; kt++) {
        int buf = kt & 1;
        if (kt + 1 < nk) {
            int k0 = (kt + 1) * TBK;
            int dstA = (buf ^ 1) * TBK * ASTR;
            int dstB = (buf ^ 1) * TBK * TBN;
            float4 mn, sc, be;
            if (BN) {
                mn = *(const float4*)&meanK[k0 + ac];
                sc = *(const float4*)&scaleK[k0 + ac];
                be = *(const float4*)&beK[k0 + ac];
            }
#pragma unroll
            for (int s = 0; s < 4; s++) {
                int m = ar + s * 32;
                int gr = rowBase + m;
                float4 v = make_float4(0.f, 0.f, 0.f, 0.f);
                if (gr < M) {
                    v = *(const float4*)&A[(size_t)gr * K + k0 + ac];
                    if (BN) {
                        v.x = fmaxf((v.x - mn.x) * sc.x + be.x, 0.f);
                        v.y = fmaxf((v.y - mn.y) * sc.y + be.y, 0.f);
                        v.z = fmaxf((v.z - mn.z) * sc.z + be.z, 0.f);
                        v.w = fmaxf((v.w - mn.w) * sc.w + be.w, 0.f);
                    }
                }
                As[dstA + (ac + 0) * ASTR + m] = v.x;
                As[dstA + (ac + 1) * ASTR + m] = v.y;
                As[dstA + (ac + 2) * ASTR + m] = v.z;
                As[dstA + (ac + 3) * ASTR + m] = v.w;
            }
#pragma unroll
            for (int s = 0; s < 4; s++) {
                int k = br + s * 8;
                *(float4*)&Bs[dstB + k * TBN + bc] =
                    *(const float4*)&B[(size_t)(k0 + k) * N + colBase + bc];
            }
        }

        const float* Ab = As + buf * TBK * ASTR;
        const float* Bb = Bs + buf * TBK * TBN;
#pragma unroll
        for (int k = 0; k < TBK; k++) {
            float a[8], b[8];
            *(float4*)&a[0] = *(const float4*)&Ab[k * ASTR + ty * 4];
            *(float4*)&a[4] = *(const float4*)&Ab[k * ASTR + ty * 4 + 64];
            *(float4*)&b[0] = *(const float4*)&Bb[k * TBN + tx * 4];
            *(float4*)&b[4] = *(const float4*)&Bb[k * TBN + tx * 4 + 64];
            unsigned long long bp[4];
#pragma unroll
            for (int j = 0; j < 4; j++)
                asm("mov.b64 %0, {%1, %2};"
                    : "=l"(bp[j]) : "f"(b[j * 2]), "f"(b[j * 2 + 1]));
#pragma unroll
            for (int i = 0; i < 8; i++) {
                unsigned long long ap;
                asm("mov.b64 %0, {%1, %1};" : "=l"(ap) : "f"(a[i]));
#pragma unroll
                for (int j = 0; j < 4; j++)
                    asm("fma.rn.f32x2 %0, %1, %2, %0;"
                        : "+l"(acc2[i][j]) : "l"(ap), "l"(bp[j]));
            }
        }
        __syncthreads();
    }

    float blo[8] = {0, 0, 0, 0, 0, 0, 0, 0};
    if (ADDB) {
        float4 bl0 = *(const float4*)&bias[colBase + tx * 4];
        float4 bl1 = *(const float4*)&bias[colBase + tx * 4 + 64];
        blo[0] = bl0.x; blo[1] = bl0.y; blo[2] = bl0.z; blo[3] = bl0.w;
        blo[4] = bl1.x; blo[5] = bl1.y; blo[6] = bl1.z; blo[7] = bl1.w;
    }

#pragma unroll
    for (int i = 0; i < 8; i++) {
        int r = (i < 4) ? (ty * 4 + i) : (ty * 4 + 64 + i - 4);
        int gr = rowBase + r;
        if (gr >= M) continue;
        size_t base = (size_t)gr * N;
#pragma unroll
        for (int jj = 0; jj < 2; jj++) {
            int c = colBase + tx * 4 + jj * 64;
            float c0, c1, c2, c3;
            asm("mov.b64 {%0, %1}, %2;" : "=f"(c0), "=f"(c1) : "l"(acc2[i][jj * 2 + 0]));
            asm("mov.b64 {%0, %1}, %2;" : "=f"(c2), "=f"(c3) : "l"(acc2[i][jj * 2 + 1]));
            float4 hv;
            if (ADDB)
                hv = make_float4(c0 + blo[jj * 4 + 0], c1 + blo[jj * 4 + 1],
                                 c2 + blo[jj * 4 + 2], c3 + blo[jj * 4 + 3]);
            else
                hv = make_float4(c0, c1, c2, c3);
            *(float4*)&OUT[base + c] = hv;
        }
    }
}

// ================= CSR gather (self-edges included; bias as init) ===============
template <bool BIAS>
__global__ void k_gather(const float* __restrict__ src, const int* __restrict__ csrc,
                         const float* __restrict__ cw, const int* __restrict__ off,
                         const float* __restrict__ bias, float* __restrict__ outp,
                         int H, int tpnshift) {
    int tpn = 1 << tpnshift;
    int local = threadIdx.x >> tpnshift;
    int node = blockIdx.x * (blockDim.x >> tpnshift) + local;
    if (node >= NN) return;
    int c = (threadIdx.x & (tpn - 1)) << 2;
    int s = __ldg(&off[node]);
    int e = __ldg(&off[node + 1]);
    float ax = 0.f, ay = 0.f, az = 0.f, aw = 0.f;
    if (BIAS) {
        float4 b = __ldg((const float4*)(bias + c));
        ax = b.x; ay = b.y; az = b.z; aw = b.w;
    }
    for (int i = s; i < e; i++) {
        int sn = __ldg(&csrc[i]);
        float w = __ldg(&cw[i]);
        float4 v = __ldg((const float4*)(src + (size_t)sn * H + c));
        ax += v.x * w; ay += v.y * w; az += v.z * w; aw += v.w * w;
    }
    *(float4*)&outp[(size_t)node * H + c] = make_float4(ax, ay, az, aw);
}

// ================= BN stats: stripe partials (fp32) + fp64 combine ==============
__global__ void k_stats_part(const float* __restrict__ x, int H,
                             float* __restrict__ psum, float* __restrict__ psqs) {
    int c = blockIdx.x * blockDim.x + threadIdx.x;
    int st = blockIdx.y;
    if (c >= H) return;
    float s = 0.f, q = 0.f;
    for (int r = st; r < NN; r += NSTR) {
        float v = x[(size_t)r * H + c];
        s += v;
        q += v * v;
    }
    psum[st * H + c] = s;
    psqs[st * H + c] = q;
}
__global__ void k_bnparam(const float* __restrict__ psum, const float* __restrict__ psqs,
                          const float* __restrict__ g, float* __restrict__ mean,
                          float* __restrict__ scale, int H) {
    int c = blockIdx.x * blockDim.x + threadIdx.x;
    if (c >= H) return;
    double s = 0.0, q = 0.0;
    for (int st = 0; st < NSTR; st++) {
        s += (double)psum[st * H + c];
        q += (double)psqs[st * H + c];
    }
    const double invN = 1.0 / (double)NN;
    double m = s * invN;
    double var = q * invN - m * m;
    mean[c] = (float)m;
    scale[c] = g[c] * (float)rsqrt(var + (double)BN_EPS);
}

// ================= graph boundaries + pool head =================================
__global__ void k_bounds(const int* __restrict__ batch, int* gstart, int n) {
    int i = blockIdx.x * blockDim.x + threadIdx.x;
    if (i >= n) return;
    int bi = batch[i];
    int bp = (i == 0) ? -1 : batch[i - 1];
    for (int g = bp + 1; g <= bi; g++) gstart[g] = i;
    if (i == n - 1)
        for (int g = bi + 1; g <= NG; g++) gstart[g] = n;
}
__global__ void k_pool_head(const float* __restrict__ agg, const int* __restrict__ gstart,
                            const float* __restrict__ mean, const float* __restrict__ scale,
                            const float* __restrict__ be, const float* __restrict__ Wo,
                            const float* __restrict__ bo, float* __restrict__ out) {
    __shared__ float pooled[128];
    int g = blockIdx.x;
    int c = threadIdx.x;
    int s = gstart[g], e = gstart[g + 1];
    float mn = mean[c], sc = scale[c], bb = be[c];
    float acc = 0.f;
    for (int n = s; n < e; n++)
        acc += fmaxf((agg[(size_t)n * 128 + c] - mn) * sc + bb, 0.f);
    float inv = 1.0f / (float)max(e - s, 1);
    pooled[c] = acc * inv;
    __syncthreads();
    if (c < 10) {
        float o = bo[c];
#pragma unroll 8
        for (int k = 0; k < 128; k++)
            o += pooled[k] * Wo[k * 10 + c];
        out[g * 10 + c] = o;
    }
}

// ================= host orchestration ===========================================
static inline int ilog2(int v) { int s = 0; while ((1 << s) < v) s++; return s; }

extern "C" void kernel_launch(void* const* d_in, const int* in_sizes, int n_in,
                              void* d_out, int out_size) {
    const float* x     = (const float*)d_in[0];
    const int*   ei    = (const int*)d_in[1];
    const int*   batch = (const int*)d_in[2];
    const float* W1 = (const float*)d_in[3];  const float* b1 = (const float*)d_in[4];
    const float* g1 = (const float*)d_in[5];  const float* be1 = (const float*)d_in[6];
    const float* W2 = (const float*)d_in[7];  const float* b2 = (const float*)d_in[8];
    const float* g2 = (const float*)d_in[9];  const float* be2 = (const float*)d_in[10];
    const float* W3 = (const float*)d_in[11]; const float* b3 = (const float*)d_in[12];
    const float* g3 = (const float*)d_in[13]; const float* be3 = (const float*)d_in[14];
    const float* Wo = (const float*)d_in[15]; const float* bo = (const float*)d_in[16];
    float* out = (float*)d_out;

    int E = in_sizes[1] / 2;
    const int* row = ei;
    const int* col = ei + E;

    float *h, *agg, *act, *dinv, *mean, *scale, *cw, *psum, *psqs;
    int *cnt, *cursor, *off, *bsum, *csrc, *gstart;
    cudaGetSymbolAddress((void**)&h, g_h);
    cudaGetSymbolAddress((void**)&agg, g_agg);
    cudaGetSymbolAddress((void**)&act, g_act);
    cudaGetSymbolAddress((void**)&dinv, g_dinv);
    cudaGetSymbolAddress((void**)&mean, g_mean);
    cudaGetSymbolAddress((void**)&scale, g_scale);
    cudaGetSymbolAddress((void**)&cw, g_cw);
    cudaGetSymbolAddress((void**)&psum, g_psum);
    cudaGetSymbolAddress((void**)&psqs, g_psqs);
    cudaGetSymbolAddress((void**)&cnt, g_cnt);
    cudaGetSymbolAddress((void**)&cursor, g_cursor);
    cudaGetSymbolAddress((void**)&off, g_off);
    cudaGetSymbolAddress((void**)&bsum, g_bsum);
    cudaGetSymbolAddress((void**)&csrc, g_csrc);
    cudaGetSymbolAddress((void**)&gstart, g_gstart);

    cudaFuncSetAttribute(k_gemm_fused<false, true>,
                         cudaFuncAttributeMaxDynamicSharedMemorySize, SMEM_GEMM);
    cudaFuncSetAttribute(k_gemm_fused<true, false>,
                         cudaFuncAttributeMaxDynamicSharedMemorySize, SMEM_GEMM);

    // ---- CSR build + dinv (self-edges included) ----
    int nb = (NN + SCAN_B - 1) / SCAN_B;
    k_zeroi<<<(NN + 255) / 256, 256>>>(cnt, NN);
    k_count<<<(E + 255) / 256, 256>>>(col, cnt, E);
    k_scan1<<<nb, SCAN_B>>>(cnt, off, bsum, NN);
    k_scan2<<<1, 32>>>(bsum, nb, off);
    if (nb > 1) k_scan3<<<nb - 1, SCAN_B>>>(off, bsum, NN);
    k_dinv2<<<(NN + 255) / 256, 256>>>(cnt, dinv, NN);
    k_selfplace<<<(NN + 255) / 256, 256>>>(off, dinv, cursor, csrc, cw, NN);
    k_place<<<(E + 255) / 256, 256>>>(row, col, dinv, off, cursor, csrc, cw, E);
    k_bounds<<<(NN + 255) / 256, 256>>>(batch, gstart, NN);

    const int GY = (NN + TBM - 1) / TBM;

    // ---- layer 1: pre-aggregate x (width 128, self-edge in CSR), GEMM+bias ----
    k_gather<false><<<(NN + 3) / 4, 128>>>(x, csrc, cw, off, nullptr, act, 128,
                                           ilog2(128 / 4));
    {
        dim3 grid(512 / TBN, GY);
        k_gemm_fused<false, true><<<grid, 256, SMEM_GEMM>>>(
            act, W1, agg, b1, nullptr, nullptr, nullptr, NN, 128, 512);
    }
    {
        dim3 sgrid((512 + 127) / 128, NSTR);
        k_stats_part<<<sgrid, 128>>>(agg, 512, psum, psqs);
    }

    // ---- layer 2: BN fused in GEMM A-load; gather adds bias ----
    k_bnparam<<<(512 + 127) / 128, 128>>>(psum, psqs, g1, mean, scale, 512);
    {
        dim3 grid(256 / TBN, GY);
        k_gemm_fused<true, false><<<grid, 256, SMEM_GEMM>>>(
            agg, W2, h, nullptr, mean, scale, be1, NN, 512, 256);
    }
    k_gather<true><<<(NN + 1) / 2, 128>>>(h, csrc, cw, off, b2, act, 256,
                                          ilog2(256 / 4));
    {
        dim3 sgrid((256 + 127) / 128, NSTR);
        k_stats_part<<<sgrid, 128>>>(act, 256, psum, psqs);
    }

    // ---- layer 3 ----
    k_bnparam<<<(256 + 127) / 128, 128>>>(psum, psqs, g2, mean, scale, 256);
    {
        dim3 grid(128 / TBN, GY);
        k_gemm_fused<true, false><<<grid, 256, SMEM_GEMM>>>(
            act, W3, h, nullptr, mean, scale, be2, NN, 256, 128);
    }
    k_gather<true><<<(NN + 3) / 4, 128>>>(h, csrc, cw, off, b3, agg, 128,
                                          ilog2(128 / 4));
    {
        dim3 sgrid(1, NSTR);
        k_stats_part<<<sgrid, 128>>>(agg, 128, psum, psqs);
    }

    // ---- final BN + pool + head ----
    k_bnparam<<<1, 128>>>(psum, psqs, g3, mean, scale, 128);
    k_pool_head<<<NG, 128>>>(agg, gstart, mean, scale, be3, Wo, bo, out);
}